// round 3
// baseline (speedup 1.0000x reference)
#include <cuda_runtime.h>
#include <cstddef>

// Problem constants (fixed by the reference)
#define BATCH 4
#define TT    2048
#define CC    1024

#define NEG_INF (__int_as_float(0xff800000))

// Scratch (allocation-free rule: __device__ globals)
__device__ float g_Qp[(size_t)BATCH * TT * CC];   // 32 MB
__device__ float g_Kp[(size_t)BATCH * TT * CC];   // 32 MB
__device__ float g_Vp[(size_t)BATCH * TT * CC];   // 32 MB
__device__ float g_S [(size_t)BATCH * TT * TT];   // 64 MB
__device__ float g_O [(size_t)BATCH * TT * CC];   // 32 MB

// ---------------------------------------------------------------------------
// GEMM-NT: C[m,n] = alpha * sum_k A[m,k]*B[n,k] (+ bias[n]) (+ causal mask)
// A: [M,K] row-major (ld=K), B: [N,K] row-major (ld=K), C: [M,N] row-major.
// blockIdx.z indexes batch via the given strides.
// Tile: 128x128x16, 256 threads, 8x8 per thread.
// ---------------------------------------------------------------------------
__global__ __launch_bounds__(256, 2)
void gemm_nt_kernel(const float* __restrict__ A, const float* __restrict__ Bm,
                    const float* __restrict__ bias, float* __restrict__ Cm,
                    int M, int N, int K,
                    size_t sA, size_t sB, size_t sC,
                    float alpha, int causal)
{
    const int bx = blockIdx.x, by = blockIdx.y, bz = blockIdx.z;
    if (causal && bx > by) return;   // upper-triangular block: never read downstream

    A  += (size_t)bz * sA;
    Bm += (size_t)bz * sB;
    Cm += (size_t)bz * sC;

    __shared__ float As[16][132];
    __shared__ float Bs[16][132];

    const int t  = threadIdx.x;          // 0..255
    const int m0 = by * 128;
    const int n0 = bx * 128;
    const int tr = (t >> 4) * 8;         // row offset of this thread's 8x8 tile
    const int tc = (t & 15) * 8;         // col offset

    float acc[8][8] = {};

    for (int k0 = 0; k0 < K; k0 += 16) {
        #pragma unroll
        for (int i = 0; i < 2; i++) {
            int idx = i * 256 + t;                 // 0..511 float4 slots
            int r   = idx >> 2;                    // 0..127
            int c   = (idx & 3) * 4;               // 0,4,8,12
            float4 fa = *(const float4*)&A [(size_t)(m0 + r) * K + k0 + c];
            As[c + 0][r] = fa.x; As[c + 1][r] = fa.y;
            As[c + 2][r] = fa.z; As[c + 3][r] = fa.w;
            float4 fb = *(const float4*)&Bm[(size_t)(n0 + r) * K + k0 + c];
            Bs[c + 0][r] = fb.x; Bs[c + 1][r] = fb.y;
            Bs[c + 2][r] = fb.z; Bs[c + 3][r] = fb.w;
        }
        __syncthreads();

        #pragma unroll
        for (int kk = 0; kk < 16; kk++) {
            float a[8], b[8];
            #pragma unroll
            for (int i = 0; i < 8; i++) a[i] = As[kk][tr + i];
            #pragma unroll
            for (int j = 0; j < 8; j++) b[j] = Bs[kk][tc + j];
            #pragma unroll
            for (int i = 0; i < 8; i++)
                #pragma unroll
                for (int j = 0; j < 8; j++)
                    acc[i][j] = fmaf(a[i], b[j], acc[i][j]);
        }
        __syncthreads();
    }

    #pragma unroll
    for (int i = 0; i < 8; i++) {
        const int row = m0 + tr + i;
        #pragma unroll
        for (int j = 0; j < 8; j++) {
            const int col = n0 + tc + j;
            float v = acc[i][j] * alpha;
            if (bias) v += bias[col];
            if (causal && col > row) v = NEG_INF;
            Cm[(size_t)row * N + col] = v;
        }
    }
}

// ---------------------------------------------------------------------------
// GEMM-NN for O = P * Vp, per batch.
// P: [T,T] row-major (probs, zeros above diagonal within valid range)
// Vp: [T,C] row-major. Only k < (rowblk+1)*128 contributes (causality).
// ---------------------------------------------------------------------------
__global__ __launch_bounds__(256, 2)
void gemm_nn_attn_kernel(const float* __restrict__ P, const float* __restrict__ V,
                         float* __restrict__ O)
{
    const int bx = blockIdx.x, by = blockIdx.y, bz = blockIdx.z;
    const float* Pb = P + (size_t)bz * TT * TT;
    const float* Vb = V + (size_t)bz * TT * CC;
    float*       Ob = O + (size_t)bz * TT * CC;

    __shared__ float As[16][132];
    __shared__ float Bs[16][132];

    const int t  = threadIdx.x;
    const int m0 = by * 128;
    const int n0 = bx * 128;
    const int kmax = (by + 1) * 128;
    const int tr = (t >> 4) * 8;
    const int tc = (t & 15) * 8;

    float acc[8][8] = {};

    for (int k0 = 0; k0 < kmax; k0 += 16) {
        #pragma unroll
        for (int i = 0; i < 2; i++) {
            int idx = i * 256 + t;
            // A tile (P rows m, cols k): transpose into As
            int r = idx >> 2;
            int c = (idx & 3) * 4;
            float4 fa = *(const float4*)&Pb[(size_t)(m0 + r) * TT + k0 + c];
            As[c + 0][r] = fa.x; As[c + 1][r] = fa.y;
            As[c + 2][r] = fa.z; As[c + 3][r] = fa.w;
            // B tile (V rows k, cols n): direct
            int kr = idx >> 5;            // 0..15
            int cc = (idx & 31) * 4;      // 0..124
            float4 fb = *(const float4*)&Vb[(size_t)(k0 + kr) * CC + n0 + cc];
            *(float4*)&Bs[kr][cc] = fb;
        }
        __syncthreads();

        #pragma unroll
        for (int kk = 0; kk < 16; kk++) {
            float a[8], b[8];
            #pragma unroll
            for (int i = 0; i < 8; i++) a[i] = As[kk][tr + i];
            #pragma unroll
            for (int j = 0; j < 8; j++) b[j] = Bs[kk][tc + j];
            #pragma unroll
            for (int i = 0; i < 8; i++)
                #pragma unroll
                for (int j = 0; j < 8; j++)
                    acc[i][j] = fmaf(a[i], b[j], acc[i][j]);
        }
        __syncthreads();
    }

    #pragma unroll
    for (int i = 0; i < 8; i++)
        #pragma unroll
        for (int j = 0; j < 8; j++)
            Ob[(size_t)(m0 + tr + i) * CC + n0 + tc + j] = acc[i][j];
}

// ---------------------------------------------------------------------------
// Row softmax over S. One block per row; valid length = ((row>>7)+1)*128.
// Entries above the diagonal inside the diagonal block are -inf -> exp = 0.
// ---------------------------------------------------------------------------
__global__ __launch_bounds__(256)
void softmax_kernel(float* __restrict__ S)
{
    const int row = blockIdx.x;
    const int b   = blockIdx.y;
    float* Sr = S + ((size_t)b * TT + row) * TT;
    const int ncols = ((row >> 7) + 1) << 7;
    const int t = threadIdx.x;

    __shared__ float red[256];

    float mx = NEG_INF;
    for (int c = t; c < ncols; c += 256) mx = fmaxf(mx, Sr[c]);
    red[t] = mx;
    __syncthreads();
    for (int s = 128; s > 0; s >>= 1) {
        if (t < s) red[t] = fmaxf(red[t], red[t + s]);
        __syncthreads();
    }
    mx = red[0];
    __syncthreads();

    float sum = 0.0f;
    for (int c = t; c < ncols; c += 256) {
        float e = expf(Sr[c] - mx);
        Sr[c] = e;
        sum += e;
    }
    red[t] = sum;
    __syncthreads();
    for (int s = 128; s > 0; s >>= 1) {
        if (t < s) red[t] += red[t + s];
        __syncthreads();
    }
    const float inv = 1.0f / red[0];

    for (int c = t; c < ncols; c += 256) Sr[c] *= inv;
}

// ---------------------------------------------------------------------------
// Launch
// ---------------------------------------------------------------------------
extern "C" void kernel_launch(void* const* d_in, const int* in_sizes, int n_in,
                              void* d_out, int out_size)
{
    const float* q   = (const float*)d_in[0];
    const float* k   = (const float*)d_in[1];
    const float* v   = (const float*)d_in[2];
    const float* Wq  = (const float*)d_in[3];
    const float* bq  = (const float*)d_in[4];
    const float* Wk  = (const float*)d_in[5];
    const float* bk  = (const float*)d_in[6];
    const float* Wv  = (const float*)d_in[7];
    const float* bv  = (const float*)d_in[8];
    const float* Wff = (const float*)d_in[9];
    const float* bff = (const float*)d_in[10];
    float* out = (float*)d_out;

    float *Qp, *Kp, *Vp, *S, *O;
    cudaGetSymbolAddress((void**)&Qp, g_Qp);
    cudaGetSymbolAddress((void**)&Kp, g_Kp);
    cudaGetSymbolAddress((void**)&Vp, g_Vp);
    cudaGetSymbolAddress((void**)&S,  g_S);
    cudaGetSymbolAddress((void**)&O,  g_O);

    const dim3 blk(256);
    const int M = BATCH * TT;   // 8192 rows for the projections

    // 1) Projections: Y = X @ W^T + b
    gemm_nt_kernel<<<dim3(CC / 128, M / 128, 1), blk>>>(
        q, Wq, bq, Qp, M, CC, CC, 0, 0, 0, 1.0f, 0);
    gemm_nt_kernel<<<dim3(CC / 128, M / 128, 1), blk>>>(
        k, Wk, bk, Kp, M, CC, CC, 0, 0, 0, 1.0f, 0);
    gemm_nt_kernel<<<dim3(CC / 128, M / 128, 1), blk>>>(
        v, Wv, bv, Vp, M, CC, CC, 0, 0, 0, 1.0f, 0);

    // 2) Scores: S = Qp @ Kp^T / sqrt(1024), causal mask (lower-tri blocks only)
    gemm_nt_kernel<<<dim3(TT / 128, TT / 128, BATCH), blk>>>(
        Qp, Kp, nullptr, S, TT, TT, CC,
        (size_t)TT * CC, (size_t)TT * CC, (size_t)TT * TT,
        1.0f / 32.0f, 1);

    // 3) Row softmax (in place)
    softmax_kernel<<<dim3(TT, BATCH), blk>>>(S);

    // 4) O = P @ Vp (triangular K range)
    gemm_nn_attn_kernel<<<dim3(CC / 128, TT / 128, BATCH), blk>>>(S, Vp, O);

    // 5) Final projection: out = O @ Wff^T + bff
    gemm_nt_kernel<<<dim3(CC / 128, M / 128, 1), blk>>>(
        O, Wff, bff, out, M, CC, CC, 0, 0, 0, 1.0f, 0);
}

// round 5
// speedup vs baseline: 2.5372x; 2.5372x over previous
#include <cuda_runtime.h>
#include <cuda_bf16.h>
#include <cstdint>
#include <cstddef>

#define BATCH 4
#define TT    2048
#define CC    1024
#define NEG_INF (__int_as_float(0xff800000))

#define BM 128
#define BN 128
#define BK 32
#define NTH 256

// SMEM layout (bf16 elements): 4 tiles of 128 rows x 40 (32 + 8 pad)
#define ROWSTR 40
#define TILE_E (128 * ROWSTR)          // 5120 elements = 10240 B
#define OFF_AH 0
#define OFF_AL (1 * TILE_E)
#define OFF_BH (2 * TILE_E)
#define OFF_BL (3 * TILE_E)
#define STAGE_E (4 * TILE_E)           // 20480 elements = 40960 B
#define SMEM_BYTES (2 * STAGE_E * 2)   // 81920 B

// Scratch (allocation-free rule: __device__ globals)
__device__ float g_Qp [(size_t)BATCH * TT * CC];
__device__ float g_Kp [(size_t)BATCH * TT * CC];
__device__ float g_VpT[(size_t)BATCH * CC * TT];   // V projection, transposed [C,T]
__device__ float g_S  [(size_t)BATCH * TT * TT];
__device__ float g_O  [(size_t)BATCH * TT * CC];

// ---------------------------------------------------------------------------
__device__ __forceinline__ void mma_bf16(float* d, const uint32_t* a, uint32_t b0, uint32_t b1) {
    asm volatile(
        "mma.sync.aligned.m16n8k16.row.col.f32.bf16.bf16.f32 "
        "{%0,%1,%2,%3},{%4,%5,%6,%7},{%8,%9},{%0,%1,%2,%3};\n"
        : "+f"(d[0]), "+f"(d[1]), "+f"(d[2]), "+f"(d[3])
        : "r"(a[0]), "r"(a[1]), "r"(a[2]), "r"(a[3]), "r"(b0), "r"(b1));
}

// split 8 fp32 into bf16 hi / lo halves (packed pairs)
__device__ __forceinline__ void cvt8(float4 a, float4 b, uint4& hi, uint4& lo) {
    float f[8] = {a.x, a.y, a.z, a.w, b.x, b.y, b.z, b.w};
    uint32_t h[4], l[4];
#pragma unroll
    for (int i = 0; i < 4; i++) {
        __nv_bfloat162 hh = __float22bfloat162_rn(make_float2(f[2*i], f[2*i+1]));
        h[i] = *reinterpret_cast<uint32_t*>(&hh);
        float r0 = f[2*i]   - __bfloat162float(hh.x);
        float r1 = f[2*i+1] - __bfloat162float(hh.y);
        __nv_bfloat162 ll = __float22bfloat162_rn(make_float2(r0, r1));
        l[i] = *reinterpret_cast<uint32_t*>(&ll);
    }
    hi = make_uint4(h[0], h[1], h[2], h[3]);
    lo = make_uint4(l[0], l[1], l[2], l[3]);
}

// ---------------------------------------------------------------------------
// Split-bf16 mma.sync GEMM-NT:
//   C[m,n] = alpha * sum_k A[m,k]*B[n,k] (+bias[n]) (+causal mask)
// transC: write C transposed per batch (V projection -> VpT)
// kvlim:  limit K to (by+1)*128 (P@V, causality)
// ---------------------------------------------------------------------------
__global__ __launch_bounds__(NTH)
void gemm_mma(const float* __restrict__ A, const float* __restrict__ B,
              const float* __restrict__ bias, float* __restrict__ C,
              int M, int N, int K,
              size_t sA, size_t sB, size_t sC,
              float alpha, int causal, int kvlim, int transC)
{
    const int bx = blockIdx.x, by = blockIdx.y, bz = blockIdx.z;
    if (causal && bx > by) return;
    A += (size_t)bz * sA;  B += (size_t)bz * sB;  C += (size_t)bz * sC;

    const int m0 = by * BM, n0 = bx * BN;
    const int Keff = kvlim ? (by + 1) * BM : K;
    const int nch  = Keff / BK;

    extern __shared__ __nv_bfloat16 sm[];

    const int t = threadIdx.x, w = t >> 5, lane = t & 31;
    const int qr = lane >> 2, qc = (lane & 3) * 2;
    const int mb = (w & 1) * 64, nb = (w >> 1) * 32;

    // load geometry: slot t -> row t>>2 (0..63), col (t&3)*8; slot t+256 -> row+64
    const int lr = t >> 2;
    const int lc = (t & 3) * 8;

    float acc[4][4][4] = {};
    float4 ra0, ra1, ra2, ra3, rb0, rb1, rb2, rb3;

    // ---- prefetch chunk 0
    {
        const float* pa = A + (size_t)(m0 + lr) * K + lc;
        ra0 = *(const float4*)pa;          ra1 = *(const float4*)(pa + 4);
        const float* pa2 = pa + (size_t)64 * K;
        ra2 = *(const float4*)pa2;         ra3 = *(const float4*)(pa2 + 4);
        const float* pb = B + (size_t)(n0 + lr) * K + lc;
        rb0 = *(const float4*)pb;          rb1 = *(const float4*)(pb + 4);
        const float* pb2 = pb + (size_t)64 * K;
        rb2 = *(const float4*)pb2;         rb3 = *(const float4*)(pb2 + 4);
    }

    for (int i = 0; i < nch; i++) {
        // ---- store prefetched regs into stage i&1
        {
            __nv_bfloat16* stg = sm + (i & 1) * STAGE_E;
            uint4 hi, lo;
            cvt8(ra0, ra1, hi, lo);
            *(uint4*)&stg[OFF_AH + lr * ROWSTR + lc] = hi;
            *(uint4*)&stg[OFF_AL + lr * ROWSTR + lc] = lo;
            cvt8(ra2, ra3, hi, lo);
            *(uint4*)&stg[OFF_AH + (lr + 64) * ROWSTR + lc] = hi;
            *(uint4*)&stg[OFF_AL + (lr + 64) * ROWSTR + lc] = lo;
            cvt8(rb0, rb1, hi, lo);
            *(uint4*)&stg[OFF_BH + lr * ROWSTR + lc] = hi;
            *(uint4*)&stg[OFF_BL + lr * ROWSTR + lc] = lo;
            cvt8(rb2, rb3, hi, lo);
            *(uint4*)&stg[OFF_BH + (lr + 64) * ROWSTR + lc] = hi;
            *(uint4*)&stg[OFF_BL + (lr + 64) * ROWSTR + lc] = lo;
        }
        __syncthreads();

        // ---- prefetch chunk i+1 (overlaps with compute below)
        if (i + 1 < nch) {
            const int k0 = (i + 1) * BK;
            const float* pa = A + (size_t)(m0 + lr) * K + k0 + lc;
            ra0 = *(const float4*)pa;          ra1 = *(const float4*)(pa + 4);
            const float* pa2 = pa + (size_t)64 * K;
            ra2 = *(const float4*)pa2;         ra3 = *(const float4*)(pa2 + 4);
            const float* pb = B + (size_t)(n0 + lr) * K + k0 + lc;
            rb0 = *(const float4*)pb;          rb1 = *(const float4*)(pb + 4);
            const float* pb2 = pb + (size_t)64 * K;
            rb2 = *(const float4*)pb2;         rb3 = *(const float4*)(pb2 + 4);
        }

        // ---- compute on stage i&1
        {
            const __nv_bfloat16* stg = sm + (i & 1) * STAGE_E;
#pragma unroll
            for (int kk = 0; kk < BK; kk += 16) {
                uint32_t bh[4][2], bl[4][2];
#pragma unroll
                for (int j = 0; j < 4; j++) {
                    const int nr = nb + j * 8 + qr;
                    bh[j][0] = *(const uint32_t*)&stg[OFF_BH + nr * ROWSTR + kk + qc];
                    bh[j][1] = *(const uint32_t*)&stg[OFF_BH + nr * ROWSTR + kk + qc + 8];
                    bl[j][0] = *(const uint32_t*)&stg[OFF_BL + nr * ROWSTR + kk + qc];
                    bl[j][1] = *(const uint32_t*)&stg[OFF_BL + nr * ROWSTR + kk + qc + 8];
                }
#pragma unroll
                for (int ii = 0; ii < 4; ii++) {
                    const int ar = mb + ii * 16 + qr;
                    uint32_t ah[4], al[4];
                    ah[0] = *(const uint32_t*)&stg[OFF_AH + ar * ROWSTR + kk + qc];
                    ah[1] = *(const uint32_t*)&stg[OFF_AH + (ar + 8) * ROWSTR + kk + qc];
                    ah[2] = *(const uint32_t*)&stg[OFF_AH + ar * ROWSTR + kk + qc + 8];
                    ah[3] = *(const uint32_t*)&stg[OFF_AH + (ar + 8) * ROWSTR + kk + qc + 8];
                    al[0] = *(const uint32_t*)&stg[OFF_AL + ar * ROWSTR + kk + qc];
                    al[1] = *(const uint32_t*)&stg[OFF_AL + (ar + 8) * ROWSTR + kk + qc];
                    al[2] = *(const uint32_t*)&stg[OFF_AL + ar * ROWSTR + kk + qc + 8];
                    al[3] = *(const uint32_t*)&stg[OFF_AL + (ar + 8) * ROWSTR + kk + qc + 8];
#pragma unroll
                    for (int j = 0; j < 4; j++) {
                        mma_bf16(acc[ii][j], ah, bh[j][0], bh[j][1]);
                        mma_bf16(acc[ii][j], ah, bl[j][0], bl[j][1]);
                        mma_bf16(acc[ii][j], al, bh[j][0], bh[j][1]);
                    }
                }
            }
        }
        __syncthreads();
    }

    // ---- epilogue
    const int diag = (causal && bx == by);
#pragma unroll
    for (int ii = 0; ii < 4; ii++) {
#pragma unroll
        for (int j = 0; j < 4; j++) {
            const int rA = m0 + mb + ii * 16 + qr;
            const int rB = rA + 8;
            const int cb = n0 + nb + j * 8 + qc;
            float v00 = acc[ii][j][0] * alpha, v01 = acc[ii][j][1] * alpha;
            float v10 = acc[ii][j][2] * alpha, v11 = acc[ii][j][3] * alpha;
            if (bias) {
                const float b0 = bias[cb], b1 = bias[cb + 1];
                v00 += b0; v01 += b1; v10 += b0; v11 += b1;
            }
            if (diag) {
                if (cb     > rA) v00 = NEG_INF;
                if (cb + 1 > rA) v01 = NEG_INF;
                if (cb     > rB) v10 = NEG_INF;
                if (cb + 1 > rB) v11 = NEG_INF;
            }
            if (transC) {
                // output [C,T] per batch: addr = batch*CC*TT + n*TT + (m % TT)
                const size_t bo = (size_t)(rA >> 11) * ((size_t)CC * TT);
                const int mA = rA & (TT - 1), mB = rB & (TT - 1);
                C[bo + (size_t)cb       * TT + mA] = v00;
                C[bo + (size_t)(cb + 1) * TT + mA] = v01;
                C[bo + (size_t)cb       * TT + mB] = v10;
                C[bo + (size_t)(cb + 1) * TT + mB] = v11;
            } else {
                *(float2*)&C[(size_t)rA * N + cb] = make_float2(v00, v01);
                *(float2*)&C[(size_t)rB * N + cb] = make_float2(v10, v11);
            }
        }
    }
}

// ---------------------------------------------------------------------------
// Row softmax over S (in place). Valid length = ((row>>7)+1)*128.
// ---------------------------------------------------------------------------
__global__ __launch_bounds__(256)
void softmax_kernel(float* __restrict__ S)
{
    const int row = blockIdx.x;
    const int b   = blockIdx.y;
    float* Sr = S + ((size_t)b * TT + row) * TT;
    const int ncols = ((row >> 7) + 1) << 7;
    const int t = threadIdx.x;

    __shared__ float red[256];

    float mx = NEG_INF;
    for (int c = t; c < ncols; c += 256) mx = fmaxf(mx, Sr[c]);
    red[t] = mx;
    __syncthreads();
    for (int s = 128; s > 0; s >>= 1) {
        if (t < s) red[t] = fmaxf(red[t], red[t + s]);
        __syncthreads();
    }
    mx = red[0];
    __syncthreads();

    float sum = 0.0f;
    for (int c = t; c < ncols; c += 256) {
        float e = expf(Sr[c] - mx);
        Sr[c] = e;
        sum += e;
    }
    red[t] = sum;
    __syncthreads();
    for (int s = 128; s > 0; s >>= 1) {
        if (t < s) red[t] += red[t + s];
        __syncthreads();
    }
    const float inv = 1.0f / red[0];
    for (int c = t; c < ncols; c += 256) Sr[c] *= inv;
}

// ---------------------------------------------------------------------------
extern "C" void kernel_launch(void* const* d_in, const int* in_sizes, int n_in,
                              void* d_out, int out_size)
{
    const float* q   = (const float*)d_in[0];
    const float* k   = (const float*)d_in[1];
    const float* v   = (const float*)d_in[2];
    const float* Wq  = (const float*)d_in[3];
    const float* bq  = (const float*)d_in[4];
    const float* Wk  = (const float*)d_in[5];
    const float* bk  = (const float*)d_in[6];
    const float* Wv  = (const float*)d_in[7];
    const float* bv  = (const float*)d_in[8];
    const float* Wff = (const float*)d_in[9];
    const float* bff = (const float*)d_in[10];
    float* out = (float*)d_out;

    float *Qp, *Kp, *VpT, *S, *O;
    cudaGetSymbolAddress((void**)&Qp,  g_Qp);
    cudaGetSymbolAddress((void**)&Kp,  g_Kp);
    cudaGetSymbolAddress((void**)&VpT, g_VpT);
    cudaGetSymbolAddress((void**)&S,   g_S);
    cudaGetSymbolAddress((void**)&O,   g_O);

    cudaFuncSetAttribute(gemm_mma, cudaFuncAttributeMaxDynamicSharedMemorySize, SMEM_BYTES);

    const dim3 blk(NTH);
    const int M = BATCH * TT;   // 8192

    // 1) Projections: Y = X @ W^T + b   (V written transposed per batch)
    gemm_mma<<<dim3(CC/BN, M/BM, 1), blk, SMEM_BYTES>>>(
        q, Wq, bq, Qp, M, CC, CC, 0, 0, 0, 1.0f, 0, 0, 0);
    gemm_mma<<<dim3(CC/BN, M/BM, 1), blk, SMEM_BYTES>>>(
        k, Wk, bk, Kp, M, CC, CC, 0, 0, 0, 1.0f, 0, 0, 0);
    gemm_mma<<<dim3(CC/BN, M/BM, 1), blk, SMEM_BYTES>>>(
        v, Wv, bv, VpT, M, CC, CC, 0, 0, 0, 1.0f, 0, 0, 1);

    // 2) Scores: S = Qp @ Kp^T / 32, causal (lower-triangular blocks only)
    gemm_mma<<<dim3(TT/BN, TT/BM, BATCH), blk, SMEM_BYTES>>>(
        Qp, Kp, nullptr, S, TT, TT, CC,
        (size_t)TT*CC, (size_t)TT*CC, (size_t)TT*TT,
        1.0f/32.0f, 1, 0, 0);

    // 3) Row softmax (in place)
    softmax_kernel<<<dim3(TT, BATCH), dim3(256)>>>(S);

    // 4) O = P @ Vp  (NT against VpT, K limited by causality)
    gemm_mma<<<dim3(CC/BN, TT/BM, BATCH), blk, SMEM_BYTES>>>(
        S, VpT, nullptr, O, TT, CC, TT,
        (size_t)TT*TT, (size_t)CC*TT, (size_t)TT*CC,
        1.0f, 0, 1, 0);

    // 5) Final projection: out = O @ Wff^T + bff
    gemm_mma<<<dim3(CC/BN, M/BM, 1), blk, SMEM_BYTES>>>(
        O, Wff, bff, out, M, CC, CC, 0, 0, 0, 1.0f, 0, 0, 0);
}